// round 1
// baseline (speedup 1.0000x reference)
#include <cuda_runtime.h>
#include <math_constants.h>

#define N 384
#define D 128
#define MARGIN 0.2f
#define RHO 10.0f

// Device-global scratch (no allocations allowed in kernel_launch)
__device__ float  g_dist[N * N];
__device__ float  g_sq[N];
__device__ double g_num;
__device__ int    g_den;

// ---------------------------------------------------------------------------
// Kernel 1: squared norms + zero accumulators
// ---------------------------------------------------------------------------
__global__ void prep_kernel(const float* __restrict__ emb) {
    int i = blockIdx.x * blockDim.x + threadIdx.x;
    if (i == 0) { g_num = 0.0; g_den = 0; }
    if (i < N) {
        const float4* row = reinterpret_cast<const float4*>(emb + i * D);
        float s = 0.0f;
#pragma unroll
        for (int q = 0; q < D / 4; q++) {
            float4 v = row[q];
            s += v.x * v.x + v.y * v.y + v.z * v.z + v.w * v.w;
        }
        g_sq[i] = s;
    }
}

// ---------------------------------------------------------------------------
// Kernel 2: pairwise squared distances (tiled 32x32 Gram), clamped at 0
// ---------------------------------------------------------------------------
__global__ void dist_kernel(const float* __restrict__ emb) {
    __shared__ float As[32][D];       // anchor rows, broadcast reads
    __shared__ float Bs[D][33];       // transposed + padded: conflict-free
    const int bi = blockIdx.y * 32;
    const int bj = blockIdx.x * 32;
    const int tid = threadIdx.x;      // 256 threads

    for (int idx = tid; idx < 32 * D; idx += 256) {
        int r = idx >> 7;             // row within tile
        int c = idx & (D - 1);        // feature index
        As[r][c] = emb[(bi + r) * D + c];
        Bs[c][r] = emb[(bj + r) * D + c];
    }
    __syncthreads();

    const int c  = tid & 31;          // output column within tile
    const int r0 = tid >> 5;          // 0..7
    float acc[4] = {0.f, 0.f, 0.f, 0.f};
    for (int d = 0; d < D; d++) {
        float b = Bs[d][c];
#pragma unroll
        for (int q = 0; q < 4; q++)
            acc[q] = fmaf(As[r0 + 8 * q][d], b, acc[q]);
    }
#pragma unroll
    for (int q = 0; q < 4; q++) {
        int i = bi + r0 + 8 * q;
        int j = bj + c;
        float dist = g_sq[i] + g_sq[j] - 2.0f * acc[q];
        g_dist[i * N + j] = fmaxf(dist, 0.0f);
    }
}

// ---------------------------------------------------------------------------
// Kernel 3: per-anchor triplet reduction. One block per anchor i.
//   Only same-class (j != i) pairs can contribute (others are exactly 0).
//   Warp w handles positive-pairs p = w, w+8, ...; lanes split the k loop.
// ---------------------------------------------------------------------------
__global__ void triplet_kernel(const int* __restrict__ classes) {
    __shared__ float  drow[N];
    __shared__ int    cls[N];
    __shared__ short  poslist[N];
    __shared__ int    npos;
    __shared__ double warpsum[8];

    const int i   = blockIdx.x;
    const int tid = threadIdx.x;      // 256 threads, 8 warps
    if (tid == 0) npos = 0;

    for (int j = tid; j < N; j += 256) {
        drow[j] = g_dist[i * N + j];
        cls[j]  = classes[j];
    }
    __syncthreads();

    const int ci = cls[i];
    for (int j = tid; j < N; j += 256) {
        if (cls[j] == ci && j != i) {
            int p = atomicAdd(&npos, 1);
            poslist[p] = (short)j;
        }
    }
    __syncthreads();

    const int np = npos;
    if (tid == 0 && np > 0) atomicAdd(&g_den, np);

    const int warp = tid >> 5;
    const int lane = tid & 31;
    double wsum = 0.0;

    for (int p = warp; p < np; p += 8) {
        const int   j   = poslist[p];
        const float dij = drow[j];
        float semimax = 0.0f;
        float shmin   = CUDART_INF_F;

        for (int k = lane; k < N; k += 32) {
            // loss = max(MARGIN - (d(i,k) - d(i,j)), 0)
            float loss  = fmaxf(MARGIN - (drow[k] - dij), 0.0f);
            bool  valid = (cls[k] != ci);
            if (valid && loss > 0.0f && loss <= MARGIN)
                semimax = fmaxf(semimax, loss);
            // shifted = loss - RHO * hard,  hard = valid && loss > MARGIN
            float sh = loss - ((valid && loss > MARGIN) ? RHO : 0.0f);
            shmin = fminf(shmin, sh);
        }
#pragma unroll
        for (int off = 16; off; off >>= 1) {
            semimax = fmaxf(semimax, __shfl_xor_sync(0xffffffffu, semimax, off));
            shmin   = fminf(shmin,   __shfl_xor_sync(0xffffffffu, shmin,   off));
        }
        float pph = (shmin < 0.0f) ? (shmin + RHO) : 0.0f;
        float ppl = semimax + ((semimax == 0.0f) ? pph : 0.0f);
        wsum += (double)ppl;          // identical across lanes after reduce
    }

    if (lane == 0) warpsum[warp] = wsum;
    __syncthreads();
    if (tid == 0) {
        double s = 0.0;
#pragma unroll
        for (int w = 0; w < 8; w++) s += warpsum[w];
        if (s != 0.0) atomicAdd(&g_num, s);
    }
}

// ---------------------------------------------------------------------------
// Kernel 4: finalize scalar
// ---------------------------------------------------------------------------
__global__ void finalize_kernel(float* __restrict__ out) {
    double den = (double)g_den;
    double r = (den > 0.0) ? (g_num / fmax(den, 1.0)) : 0.0;
    out[0] = (float)r;
}

// ---------------------------------------------------------------------------
extern "C" void kernel_launch(void* const* d_in, const int* in_sizes, int n_in,
                              void* d_out, int out_size) {
    const int*   classes = (const int*)d_in[0];
    const float* emb     = (const float*)d_in[1];

    prep_kernel<<<3, 128>>>(emb);
    dim3 grid(N / 32, N / 32);        // 12 x 12
    dist_kernel<<<grid, 256>>>(emb);
    triplet_kernel<<<N, 256>>>(classes);
    finalize_kernel<<<1, 1>>>((float*)d_out);
}